// round 16
// baseline (speedup 1.0000x reference)
#include <cuda_runtime.h>
#include <cuda_bf16.h>

// FSRCNN: BS=1024, D=56, S=12, H=W=32 -> out 3x64x64
__device__ float g_h1[1024 * 12 * 1024];   // after b0 + prelu
__device__ float g_h5[1024 * 12 * 1024];   // after b4 + prelu(b5_a)
__device__ float g_cpack[5064];            // staging: head constants

// constant-bank image: [0:4256) wh padded [oc][76], [4256:4928) w0t [oc][12],
// [4928:4984) hb, [4984:5040) ha, [5040:5052) b0b, [5052:5064) b0a
__constant__ __align__(16) float c_head[5064];

typedef unsigned long long ull;
__device__ __forceinline__ ull pk2(float lo, float hi) {
    ull r; asm("mov.b64 %0,{%1,%2};" : "=l"(r) : "f"(lo), "f"(hi)); return r;
}
__device__ __forceinline__ float2 upk2(ull v) {
    float2 o; asm("mov.b64 {%0,%1},%2;" : "=f"(o.x), "=f"(o.y) : "l"(v)); return o;
}
__device__ __forceinline__ ull ffma2(ull a, ull b, ull c) {
    ull d; asm("fma.rn.f32x2 %0,%1,%2,%3;" : "=l"(d) : "l"(a), "l"(b), "l"(c)); return d;
}

// ---------------------------------------------------------------------------
// Prep: pack head weights (padded/transposed) into g_cpack for the const copy.
// ---------------------------------------------------------------------------
__global__ __launch_bounds__(256) void k_prep(
    const float* __restrict__ head_w, const float* __restrict__ head_b,
    const float* __restrict__ head_a,
    const float* __restrict__ b0_w, const float* __restrict__ b0_b,
    const float* __restrict__ b0_a)
{
    const int i = blockIdx.x * 256 + threadIdx.x;
    if (i < 4256) {
        const int oc = i / 76, t = i % 76;
        g_cpack[i] = (t < 75) ? head_w[oc * 75 + t] : 0.f;
    } else if (i < 4928) {
        const int j = i - 4256;
        const int oc = j / 12, s = j % 12;
        g_cpack[i] = b0_w[s * 56 + oc];
    } else if (i < 4984) {
        g_cpack[i] = head_b[i - 4928];
    } else if (i < 5040) {
        g_cpack[i] = head_a[i - 4984];
    } else if (i < 5052) {
        g_cpack[i] = b0_b[i - 5040];
    } else if (i < 5064) {
        g_cpack[i] = b0_a[i - 5052];
    }
}

// ---------------------------------------------------------------------------
// Kernel 1: head 5x5 conv (3->56, pad2) + PReLU + b0 1x1 (56->12) + PReLU
// TWO pixels processed jointly per oc pass -> weight LDC traffic halves.
// ---------------------------------------------------------------------------
__global__ __launch_bounds__(256, 1) void k_head(const float* __restrict__ x)
{
    __shared__ float xs[3 * 1024];

    const int tid = threadIdx.x;
    const int img = blockIdx.x;

    const float* xim = x + img * 3072;
    for (int i = tid; i < 3072; i += 256) xs[i] = xim[i];
    __syncthreads();

    float* out = g_h1 + img * 12288;

#pragma unroll 1
    for (int k = 0; k < 2; k++) {
        const int pixA = k * 512 + tid;
        const int pixB = pixA + 256;
        const int yA = pixA >> 5, xA = pixA & 31;
        const int yB = pixB >> 5, xB = pixB & 31;

        ull xpA[38], xpB[38];
        {
            float xrA[76], xrB[76];
            xrA[75] = 0.f; xrB[75] = 0.f;
#pragma unroll
            for (int ic = 0; ic < 3; ic++)
#pragma unroll
            for (int ky = 0; ky < 5; ky++) {
                const int yyA = yA + ky - 2;
                const int yyB = yB + ky - 2;
#pragma unroll
                for (int kx = 0; kx < 5; kx++) {
                    const int xxA = xA + kx - 2;
                    const int xxB = xB + kx - 2;
                    const bool okA = (yyA >= 0) & (yyA < 32) & (xxA >= 0) & (xxA < 32);
                    const bool okB = (yyB >= 0) & (yyB < 32) & (xxB >= 0) & (xxB < 32);
                    xrA[ic * 25 + ky * 5 + kx] = okA ? xs[ic * 1024 + yyA * 32 + xxA] : 0.f;
                    xrB[ic * 25 + ky * 5 + kx] = okB ? xs[ic * 1024 + yyB * 32 + xxB] : 0.f;
                }
            }
#pragma unroll
            for (int j = 0; j < 38; j++) {
                xpA[j] = pk2(xrA[2 * j], xrA[2 * j + 1]);
                xpB[j] = pk2(xrB[2 * j], xrB[2 * j + 1]);
            }
        }

        ull accA[6], accB[6];
#pragma unroll
        for (int p = 0; p < 6; p++) {
            const ull b = pk2(c_head[5040 + 2 * p], c_head[5041 + 2 * p]);
            accA[p] = b; accB[p] = b;
        }

#pragma unroll 1
        for (int oc = 0; oc < 56; oc++) {
            const ulonglong2* wp = (const ulonglong2*)(c_head + oc * 76);
            ull a0 = 0ULL, a1 = 0ULL, b0 = 0ULL, b1 = 0ULL;
#pragma unroll
            for (int j = 0; j < 19; j++) {
                const ulonglong2 w = wp[j];
                a0 = ffma2(xpA[2 * j],     w.x, a0);
                a1 = ffma2(xpA[2 * j + 1], w.y, a1);
                b0 = ffma2(xpB[2 * j],     w.x, b0);
                b1 = ffma2(xpB[2 * j + 1], w.y, b1);
            }
            const float2 sa0 = upk2(a0), sa1 = upk2(a1);
            const float2 sb0 = upk2(b0), sb1 = upk2(b1);
            const float hbias = c_head[4928 + oc], halpha = c_head[4984 + oc];
            float va = hbias + ((sa0.x + sa0.y) + (sa1.x + sa1.y));
            float vb = hbias + ((sb0.x + sb0.y) + (sb1.x + sb1.y));
            va = (va >= 0.f) ? va : halpha * va;
            vb = (vb >= 0.f) ? vb : halpha * vb;
            const ull ha = pk2(va, va);
            const ull hb = pk2(vb, vb);
            const ulonglong2* q = (const ulonglong2*)(c_head + 4256 + oc * 12);
            const ulonglong2 q0 = q[0], q1 = q[1], q2 = q[2];
            accA[0] = ffma2(ha, q0.x, accA[0]);  accB[0] = ffma2(hb, q0.x, accB[0]);
            accA[1] = ffma2(ha, q0.y, accA[1]);  accB[1] = ffma2(hb, q0.y, accB[1]);
            accA[2] = ffma2(ha, q1.x, accA[2]);  accB[2] = ffma2(hb, q1.x, accB[2]);
            accA[3] = ffma2(ha, q1.y, accA[3]);  accB[3] = ffma2(hb, q1.y, accB[3]);
            accA[4] = ffma2(ha, q2.x, accA[4]);  accB[4] = ffma2(hb, q2.x, accB[4]);
            accA[5] = ffma2(ha, q2.y, accA[5]);  accB[5] = ffma2(hb, q2.y, accB[5]);
        }

#pragma unroll
        for (int p = 0; p < 6; p++) {
            const float2 uA = upk2(accA[p]);
            const float2 uB = upk2(accB[p]);
            const float al0 = c_head[5052 + 2 * p], al1 = c_head[5053 + 2 * p];
            float a0v = uA.x, a1v = uA.y, b0v = uB.x, b1v = uB.y;
            a0v = (a0v >= 0.f) ? a0v : al0 * a0v;
            a1v = (a1v >= 0.f) ? a1v : al1 * a1v;
            b0v = (b0v >= 0.f) ? b0v : al0 * b0v;
            b1v = (b1v >= 0.f) ? b1v : al1 * b1v;
            out[(2 * p) * 1024 + pixA]     = a0v;
            out[(2 * p + 1) * 1024 + pixA] = a1v;
            out[(2 * p) * 1024 + pixB]     = b0v;
            out[(2 * p + 1) * 1024 + pixB] = b1v;
        }
    }
}

// ---------------------------------------------------------------------------
// Kernel 2: four 3x3 convs (12->12, pad1), PReLU(b5_a) after the last.
// Padded 34x34 smem image; f32x2 over oc-pairs, weights [l][ic][tap][oc12].
// ---------------------------------------------------------------------------
__global__ __launch_bounds__(256, 2) void k_body(
    const float* __restrict__ w1, const float* __restrict__ bb1,
    const float* __restrict__ w2, const float* __restrict__ bb2,
    const float* __restrict__ w3, const float* __restrict__ bb3,
    const float* __restrict__ w4, const float* __restrict__ bb4,
    const float* __restrict__ b5a)
{
    extern __shared__ float sm[];
    float* buf = sm;               // 12*1156 = 13872 (34x34 padded)
    float* ws  = sm + 13872;       // 4*1296 = 5184, [l][ic][tap9][oc12]
    float* bs  = sm + 19056;       // 48
    float* a5  = sm + 19104;       // 12

    const int tid = threadIdx.x;
    const int img = blockIdx.x;

    const float* wl[4] = {w1, w2, w3, w4};
    const float* bl[4] = {bb1, bb2, bb3, bb4};
    for (int i = tid; i < 5184; i += 256) {
        const int l = i / 1296;
        const int r = i % 1296;
        const int ic = r / 108;
        const int r2 = r % 108;
        const int t = r2 / 12;
        const int oc = r2 % 12;
        ws[i] = wl[l][(oc * 12 + ic) * 9 + t];
    }
    if (tid < 48) bs[tid] = bl[tid / 12][tid % 12];
    if (tid < 12) a5[tid] = b5a[tid];

    for (int i = tid; i < 13872; i += 256) buf[i] = 0.f;
    __syncthreads();

    const float* src_g = g_h1 + img * 12288;
    for (int i = tid; i < 12288; i += 256) {
        const int c = i >> 10, p = i & 1023;
        const int y = p >> 5, xx = p & 31;
        buf[c * 1156 + (y + 1) * 34 + (xx + 1)] = src_g[i];
    }
    __syncthreads();

    const int x = tid & 31;
    const int y0 = tid >> 5;
    int base[4];
#pragma unroll
    for (int k = 0; k < 4; k++) base[k] = (y0 + 8 * k + 1) * 34 + (x + 1);

    float* gout = g_h5 + img * 12288;

#pragma unroll 1
    for (int l = 0; l < 4; l++) {
        const float* wsl = ws + l * 1296;
        const float* bb = bs + l * 12;

        ull acc2[4][6];
#pragma unroll
        for (int k = 0; k < 4; k++)
#pragma unroll
            for (int p = 0; p < 6; p++) acc2[k][p] = pk2(bb[2 * p], bb[2 * p + 1]);

#pragma unroll 1
        for (int ic = 0; ic < 12; ic++) {
            const float* cb = buf + ic * 1156;
            float n[4][9];
#pragma unroll
            for (int k = 0; k < 4; k++) {
                const float* sp = cb + base[k];
                n[k][0] = sp[-35]; n[k][1] = sp[-34]; n[k][2] = sp[-33];
                n[k][3] = sp[-1];  n[k][4] = sp[0];   n[k][5] = sp[1];
                n[k][6] = sp[33];  n[k][7] = sp[34];  n[k][8] = sp[35];
            }
            const float* wic = wsl + ic * 108;
#pragma unroll
            for (int t = 0; t < 9; t++) {
                const ulonglong2* wt = (const ulonglong2*)(wic + t * 12);
                const ulonglong2 wA = wt[0];
                const ull wC = *(const ull*)(wic + t * 12 + 4);
                const ulonglong2 wB = *(const ulonglong2*)(wic + t * 12 + 6);
#pragma unroll
                for (int k = 0; k < 4; k++) {
                    const ull nb = pk2(n[k][t], n[k][t]);
                    acc2[k][0] = ffma2(nb, wA.x, acc2[k][0]);
                    acc2[k][1] = ffma2(nb, wA.y, acc2[k][1]);
                    acc2[k][2] = ffma2(nb, wC,   acc2[k][2]);
                    acc2[k][3] = ffma2(nb, wB.x, acc2[k][3]);
                    acc2[k][4] = ffma2(nb, wB.y, acc2[k][4]);
                    acc2[k][5] = ffma2(nb, *(const ull*)(wic + t * 12 + 10), acc2[k][5]);
                }
            }
        }

        if (l == 3) {
#pragma unroll
            for (int k = 0; k < 4; k++) {
                const int pix = k * 256 + tid;
#pragma unroll
                for (int p = 0; p < 6; p++) {
                    const float2 u = upk2(acc2[k][p]);
                    float v0 = u.x, v1 = u.y;
                    v0 = (v0 >= 0.f) ? v0 : a5[2 * p] * v0;
                    v1 = (v1 >= 0.f) ? v1 : a5[2 * p + 1] * v1;
                    gout[(2 * p) * 1024 + pix]     = v0;
                    gout[(2 * p + 1) * 1024 + pix] = v1;
                }
            }
        } else {
            __syncthreads();
#pragma unroll
            for (int k = 0; k < 4; k++)
#pragma unroll
                for (int p = 0; p < 6; p++) {
                    const float2 u = upk2(acc2[k][p]);
                    buf[(2 * p) * 1156 + base[k]]     = u.x;
                    buf[(2 * p + 1) * 1156 + base[k]] = u.y;
                }
            __syncthreads();
        }
    }
}

// ---------------------------------------------------------------------------
// Kernel 3: b6 1x1 (12->56) + PReLU in smem, then 9x9 stride-2 transposed
// conv (56->3). 512 threads, 2 HORIZONTALLY-ADJACENT sites per thread
// ((sy,2m),(sy,2m+1)) -> shared h columns (6 loads cover both sites' 5 taps)
// AND shared tap weights. h6c layout [row36][blk18][60]: column pair packed
// per 60-float block (odd group stride -> conflict-free LDS.128).
// ---------------------------------------------------------------------------
__device__ __forceinline__ void cls2(const ulonglong2 h0, const ulonglong2 h1,
                                     const float* wt, int g, ull* P)
{
    const ulonglong2 w0 = *(const ulonglong2*)(wt + g);
    const ulonglong2 w1 = *(const ulonglong2*)(wt + 28 + g);
    const ulonglong2 w2 = *(const ulonglong2*)(wt + 56 + g);
    P[0] = ffma2(h0.x, w0.x, P[0]); P[0] = ffma2(h0.y, w0.y, P[0]);
    P[1] = ffma2(h0.x, w1.x, P[1]); P[1] = ffma2(h0.y, w1.y, P[1]);
    P[2] = ffma2(h0.x, w2.x, P[2]); P[2] = ffma2(h0.y, w2.y, P[2]);
    P[3] = ffma2(h1.x, w0.x, P[3]); P[3] = ffma2(h1.y, w0.y, P[3]);
    P[4] = ffma2(h1.x, w1.x, P[4]); P[4] = ffma2(h1.y, w1.y, P[4]);
    P[5] = ffma2(h1.x, w2.x, P[5]); P[5] = ffma2(h1.y, w2.y, P[5]);
}

__global__ __launch_bounds__(512, 1) void k_tail(
    const float* __restrict__ b6_w, const float* __restrict__ b6_b,
    const float* __restrict__ b6_a,
    const float* __restrict__ tail_w, const float* __restrict__ tail_b,
    float* __restrict__ out)
{
    extern __shared__ float sm[];
    float* h6c = sm;            // 36*18*60 = 38880  [row][blk][60]
    float* wtc = sm + 38880;    // 81*3*28 = 6804    [tap][oc][cl]
    float* b6w = sm + 45684;    // 672
    float* b6b = sm + 46356;    // 56
    float* b6a = sm + 46412;    // 56
    float* tb  = sm + 46468;    // 4
    // total 46472 floats = 185888 B

    const int tid = threadIdx.x;
    const int img = blockIdx.x;

    const float* h5g = g_h5 + img * 12288;

    for (int i = tid; i < 672; i += 512) b6w[i] = b6_w[i];
    if (tid < 56) { b6b[tid] = b6_b[tid]; b6a[tid] = b6_a[tid]; }
    if (tid < 3) tb[tid] = tail_b[tid];
    __syncthreads();

    const int sy = tid >> 4;     // 0..31
    const int m  = tid & 15;     // site cols 2m, 2m+1

    ull acc[4][6];   // [parity ry*2+rx][site0 oc0..2, site1 oc0..2]
#pragma unroll
    for (int p = 0; p < 4; p++)
#pragma unroll
        for (int o = 0; o < 6; o++) acc[p][o] = 0ULL;

#pragma unroll 1
    for (int cc = 0; cc < 2; cc++) {
        const int cb56 = cc * 28;
        if (cc) __syncthreads();    // protect wtc/h6c from previous readers

        // stage tail-weight chunk [tap81][oc3][cl28]
        for (int i = tid; i < 6804; i += 512) {
            const int tap = i / 84;
            const int rest = i % 84;
            const int oc = rest / 28;
            const int cl = rest % 28;
            wtc[i] = tail_w[(cb56 + cl) * 243 + oc * 81 + tap];
        }

        // phase A: expand 12 -> 28 channels for up to 3 tile pixels.
#pragma unroll 1
        for (int pp = 0; pp < 3; pp++) {
            const int p = tid + pp * 512;
            if (p >= 1296) break;
            const int r = p / 36, s = p % 36;
            const int iy = r - 2, ix = s - 2;
            const bool valid = (iy >= 0) & (iy < 32) & (ix >= 0) & (ix < 32);
            const float* gp = h5g + iy * 32 + ix;
            float v[12];
#pragma unroll
            for (int c = 0; c < 12; c++)
                v[c] = valid ? __ldg(gp + c * 1024) : 0.f;

            float* hout = h6c + r * 1080 + (s >> 1) * 60 + (s & 1) * 28;
#pragma unroll 1
            for (int cl = 0; cl < 28; cl++) {
                const int c = cb56 + cl;
                const float4* wq = (const float4*)(b6w + c * 12);
                const float4 q0 = wq[0], q1 = wq[1], q2 = wq[2];
                float a = b6b[c];
                a = fmaf(v[0], q0.x, a);  a = fmaf(v[1], q0.y, a);
                a = fmaf(v[2], q0.z, a);  a = fmaf(v[3], q0.w, a);
                a = fmaf(v[4], q1.x, a);  a = fmaf(v[5], q1.y, a);
                a = fmaf(v[6], q1.z, a);  a = fmaf(v[7], q1.w, a);
                a = fmaf(v[8], q2.x, a);  a = fmaf(v[9], q2.y, a);
                a = fmaf(v[10], q2.z, a); a = fmaf(v[11], q2.w, a);
                a = (a >= 0.f) ? a : b6a[c] * a;
                hout[cl] = valid ? a : 0.f;
            }
        }
        __syncthreads();

        // phase B: 5 rows x 6 shared h-columns; taps map to both sites.
        // dr = 0 (ky=8 only)
        {
            const float* hr = h6c + sy * 1080 + m * 60;
            const float* wk = wtc + (8 * 9) * 84;
#pragma unroll 1
            for (int g = 0; g < 28; g += 4) {
                const ulonglong2 hA0 = *(const ulonglong2*)(hr + g);
                const ulonglong2 hA1 = *(const ulonglong2*)(hr + 28 + g);
                const ulonglong2 hB0 = *(const ulonglong2*)(hr + 60 + g);
                const ulonglong2 hB1 = *(const ulonglong2*)(hr + 88 + g);
                const ulonglong2 hC0 = *(const ulonglong2*)(hr + 120 + g);
                const ulonglong2 hC1 = *(const ulonglong2*)(hr + 148 + g);
                cls2(hA0, hA1, wk + 8 * 84, g, acc[0]);
                cls2(hA1, hB0, wk + 6 * 84, g, acc[0]);
                cls2(hA1, hB0, wk + 7 * 84, g, acc[1]);
                cls2(hB0, hB1, wk + 4 * 84, g, acc[0]);
                cls2(hB0, hB1, wk + 5 * 84, g, acc[1]);
                cls2(hB1, hC0, wk + 2 * 84, g, acc[0]);
                cls2(hB1, hC0, wk + 3 * 84, g, acc[1]);
                cls2(hC0, hC1, wk + 0 * 84, g, acc[0]);
                cls2(hC0, hC1, wk + 1 * 84, g, acc[1]);
            }
        }
#pragma unroll 1
        for (int dr = 1; dr < 5; dr++) {
            const int ky0 = 8 - 2 * dr, ky1 = 9 - 2 * dr;
            const float* hr = h6c + (sy + dr) * 1080 + m * 60;
            const float* w0r = wtc + ky0 * 9 * 84;
            const float* w1r = wtc + ky1 * 9 * 84;
#pragma unroll 1
            for (int g = 0; g < 28; g += 4) {
                const ulonglong2 hA0 = *(const ulonglong2*)(hr + g);
                const ulonglong2 hA1 = *(const ulonglong2*)(hr + 28 + g);
                const ulonglong2 hB0 = *(const ulonglong2*)(hr + 60 + g);
                const ulonglong2 hB1 = *(const ulonglong2*)(hr + 88 + g);
                const ulonglong2 hC0 = *(const ulonglong2*)(hr + 120 + g);
                const ulonglong2 hC1 = *(const ulonglong2*)(hr + 148 + g);
                cls2(hA0, hA1, w0r + 8 * 84, g, acc[0]);
                cls2(hA1, hB0, w0r + 6 * 84, g, acc[0]);
                cls2(hA1, hB0, w0r + 7 * 84, g, acc[1]);
                cls2(hB0, hB1, w0r + 4 * 84, g, acc[0]);
                cls2(hB0, hB1, w0r + 5 * 84, g, acc[1]);
                cls2(hB1, hC0, w0r + 2 * 84, g, acc[0]);
                cls2(hB1, hC0, w0r + 3 * 84, g, acc[1]);
                cls2(hC0, hC1, w0r + 0 * 84, g, acc[0]);
                cls2(hC0, hC1, w0r + 1 * 84, g, acc[1]);

                cls2(hA0, hA1, w1r + 8 * 84, g, acc[2]);
                cls2(hA1, hB0, w1r + 6 * 84, g, acc[2]);
                cls2(hA1, hB0, w1r + 7 * 84, g, acc[3]);
                cls2(hB0, hB1, w1r + 4 * 84, g, acc[2]);
                cls2(hB0, hB1, w1r + 5 * 84, g, acc[3]);
                cls2(hB1, hC0, w1r + 2 * 84, g, acc[2]);
                cls2(hB1, hC0, w1r + 3 * 84, g, acc[3]);
                cls2(hC0, hC1, w1r + 0 * 84, g, acc[2]);
                cls2(hC0, hC1, w1r + 1 * 84, g, acc[3]);
            }
        }
    }

    float* o = out + img * 3 * 4096;
#pragma unroll
    for (int par = 0; par < 4; par++) {
        const int ry = par >> 1, rx = par & 1;
        const int oy = 2 * sy + ry;
        const int ox0 = 4 * m + rx;       // site0 (col 2m)
        const int ox1 = 4 * m + 2 + rx;   // site1 (col 2m+1)
#pragma unroll
        for (int oc = 0; oc < 3; oc++) {
            const float2 u0 = upk2(acc[par][oc]);
            const float2 u1 = upk2(acc[par][3 + oc]);
            o[oc * 4096 + oy * 64 + ox0] = tb[oc] + (u0.x + u0.y);
            o[oc * 4096 + oy * 64 + ox1] = tb[oc] + (u1.x + u1.y);
        }
    }
}

// ---------------------------------------------------------------------------
extern "C" void kernel_launch(void* const* d_in, const int* in_sizes, int n_in,
                              void* d_out, int out_size)
{
    const float* x      = (const float*)d_in[0];
    const float* head_w = (const float*)d_in[1];
    const float* head_b = (const float*)d_in[2];
    const float* head_a = (const float*)d_in[3];
    const float* b0_w   = (const float*)d_in[4];
    const float* b0_b   = (const float*)d_in[5];
    const float* b0_a   = (const float*)d_in[6];
    const float* b1_w   = (const float*)d_in[7];
    const float* b1_b   = (const float*)d_in[8];
    const float* b2_w   = (const float*)d_in[9];
    const float* b2_b   = (const float*)d_in[10];
    const float* b3_w   = (const float*)d_in[11];
    const float* b3_b   = (const float*)d_in[12];
    const float* b4_w   = (const float*)d_in[13];
    const float* b4_b   = (const float*)d_in[14];
    const float* b5_a   = (const float*)d_in[15];
    const float* b6_w   = (const float*)d_in[16];
    const float* b6_b   = (const float*)d_in[17];
    const float* b6_a   = (const float*)d_in[18];
    const float* tail_w = (const float*)d_in[19];
    const float* tail_b = (const float*)d_in[20];

    const int SM2 = 19116 * 4;   // k_body dynamic smem (76.5 KB)
    const int SM4 = 46472 * 4;   // k_tail dynamic smem (185.9 KB)
    cudaFuncSetAttribute(k_body, cudaFuncAttributeMaxDynamicSharedMemorySize, SM2);
    cudaFuncSetAttribute(k_tail, cudaFuncAttributeMaxDynamicSharedMemorySize, SM4);

    // stage head weights into constant bank (graph-capturable D2D copy)
    k_prep<<<20, 256>>>(head_w, head_b, head_a, b0_w, b0_b, b0_a);
    void* gsrc = nullptr;  cudaGetSymbolAddress(&gsrc, g_cpack);
    void* cdst = nullptr;  cudaGetSymbolAddress(&cdst, c_head);
    cudaMemcpyAsync(cdst, gsrc, 5064 * sizeof(float), cudaMemcpyDeviceToDevice, 0);

    k_head<<<1024, 256>>>(x);
    k_body<<<1024, 256, SM2>>>(b1_w, b1_b, b2_w, b2_b, b3_w, b3_b, b4_w, b4_b, b5_a);
    k_tail<<<1024, 512, SM4>>>(b6_w, b6_b, b6_a, tail_w, tail_b, (float*)d_out);
}

// round 17
// speedup vs baseline: 1.6124x; 1.6124x over previous
#include <cuda_runtime.h>
#include <cuda_bf16.h>

// FSRCNN: BS=1024, D=56, S=12, H=W=32 -> out 3x64x64
__device__ float g_h1[1024 * 12 * 1024];   // after b0 + prelu
__device__ float g_h5[1024 * 12 * 1024];   // after b4 + prelu(b5_a)
__device__ float g_cpack[5064];            // staging: head constants

// constant-bank image: [0:4256) wh padded [oc][76], [4256:4928) w0t [oc][12],
// [4928:4984) hb, [4984:5040) ha, [5040:5052) b0b, [5052:5064) b0a
__constant__ __align__(16) float c_head[5064];

typedef unsigned long long ull;
__device__ __forceinline__ ull pk2(float lo, float hi) {
    ull r; asm("mov.b64 %0,{%1,%2};" : "=l"(r) : "f"(lo), "f"(hi)); return r;
}
__device__ __forceinline__ float2 upk2(ull v) {
    float2 o; asm("mov.b64 {%0,%1},%2;" : "=f"(o.x), "=f"(o.y) : "l"(v)); return o;
}
__device__ __forceinline__ ull ffma2(ull a, ull b, ull c) {
    ull d; asm("fma.rn.f32x2 %0,%1,%2,%3;" : "=l"(d) : "l"(a), "l"(b), "l"(c)); return d;
}

// ---------------------------------------------------------------------------
// Prep: pack head weights (padded/transposed) into g_cpack for the const copy.
// ---------------------------------------------------------------------------
__global__ __launch_bounds__(256) void k_prep(
    const float* __restrict__ head_w, const float* __restrict__ head_b,
    const float* __restrict__ head_a,
    const float* __restrict__ b0_w, const float* __restrict__ b0_b,
    const float* __restrict__ b0_a)
{
    const int i = blockIdx.x * 256 + threadIdx.x;
    if (i < 4256) {
        const int oc = i / 76, t = i % 76;
        g_cpack[i] = (t < 75) ? head_w[oc * 75 + t] : 0.f;
    } else if (i < 4928) {
        const int j = i - 4256;
        const int oc = j / 12, s = j % 12;
        g_cpack[i] = b0_w[s * 56 + oc];
    } else if (i < 4984) {
        g_cpack[i] = head_b[i - 4928];
    } else if (i < 5040) {
        g_cpack[i] = head_a[i - 4984];
    } else if (i < 5052) {
        g_cpack[i] = b0_b[i - 5040];
    } else if (i < 5064) {
        g_cpack[i] = b0_a[i - 5052];
    }
}

// ---------------------------------------------------------------------------
// Kernel 1: head 5x5 conv (3->56, pad2) + PReLU + b0 1x1 (56->12) + PReLU
// TWO pixels processed jointly per oc pass -> weight LDC traffic halves.
// ---------------------------------------------------------------------------
__global__ __launch_bounds__(256, 1) void k_head(const float* __restrict__ x)
{
    __shared__ float xs[3 * 1024];

    const int tid = threadIdx.x;
    const int img = blockIdx.x;

    const float* xim = x + img * 3072;
    for (int i = tid; i < 3072; i += 256) xs[i] = xim[i];
    __syncthreads();

    float* out = g_h1 + img * 12288;

#pragma unroll 1
    for (int k = 0; k < 2; k++) {
        const int pixA = k * 512 + tid;
        const int pixB = pixA + 256;
        const int yA = pixA >> 5, xA = pixA & 31;
        const int yB = pixB >> 5, xB = pixB & 31;

        ull xpA[38], xpB[38];
        {
            float xrA[76], xrB[76];
            xrA[75] = 0.f; xrB[75] = 0.f;
#pragma unroll
            for (int ic = 0; ic < 3; ic++)
#pragma unroll
            for (int ky = 0; ky < 5; ky++) {
                const int yyA = yA + ky - 2;
                const int yyB = yB + ky - 2;
#pragma unroll
                for (int kx = 0; kx < 5; kx++) {
                    const int xxA = xA + kx - 2;
                    const int xxB = xB + kx - 2;
                    const bool okA = (yyA >= 0) & (yyA < 32) & (xxA >= 0) & (xxA < 32);
                    const bool okB = (yyB >= 0) & (yyB < 32) & (xxB >= 0) & (xxB < 32);
                    xrA[ic * 25 + ky * 5 + kx] = okA ? xs[ic * 1024 + yyA * 32 + xxA] : 0.f;
                    xrB[ic * 25 + ky * 5 + kx] = okB ? xs[ic * 1024 + yyB * 32 + xxB] : 0.f;
                }
            }
#pragma unroll
            for (int j = 0; j < 38; j++) {
                xpA[j] = pk2(xrA[2 * j], xrA[2 * j + 1]);
                xpB[j] = pk2(xrB[2 * j], xrB[2 * j + 1]);
            }
        }

        ull accA[6], accB[6];
#pragma unroll
        for (int p = 0; p < 6; p++) {
            const ull b = pk2(c_head[5040 + 2 * p], c_head[5041 + 2 * p]);
            accA[p] = b; accB[p] = b;
        }

#pragma unroll 1
        for (int oc = 0; oc < 56; oc++) {
            const ulonglong2* wp = (const ulonglong2*)(c_head + oc * 76);
            ull a0 = 0ULL, a1 = 0ULL, b0 = 0ULL, b1 = 0ULL;
#pragma unroll
            for (int j = 0; j < 19; j++) {
                const ulonglong2 w = wp[j];
                a0 = ffma2(xpA[2 * j],     w.x, a0);
                a1 = ffma2(xpA[2 * j + 1], w.y, a1);
                b0 = ffma2(xpB[2 * j],     w.x, b0);
                b1 = ffma2(xpB[2 * j + 1], w.y, b1);
            }
            const float2 sa0 = upk2(a0), sa1 = upk2(a1);
            const float2 sb0 = upk2(b0), sb1 = upk2(b1);
            const float hbias = c_head[4928 + oc], halpha = c_head[4984 + oc];
            float va = hbias + ((sa0.x + sa0.y) + (sa1.x + sa1.y));
            float vb = hbias + ((sb0.x + sb0.y) + (sb1.x + sb1.y));
            va = (va >= 0.f) ? va : halpha * va;
            vb = (vb >= 0.f) ? vb : halpha * vb;
            const ull ha = pk2(va, va);
            const ull hb = pk2(vb, vb);
            const ulonglong2* q = (const ulonglong2*)(c_head + 4256 + oc * 12);
            const ulonglong2 q0 = q[0], q1 = q[1], q2 = q[2];
            accA[0] = ffma2(ha, q0.x, accA[0]);  accB[0] = ffma2(hb, q0.x, accB[0]);
            accA[1] = ffma2(ha, q0.y, accA[1]);  accB[1] = ffma2(hb, q0.y, accB[1]);
            accA[2] = ffma2(ha, q1.x, accA[2]);  accB[2] = ffma2(hb, q1.x, accB[2]);
            accA[3] = ffma2(ha, q1.y, accA[3]);  accB[3] = ffma2(hb, q1.y, accB[3]);
            accA[4] = ffma2(ha, q2.x, accA[4]);  accB[4] = ffma2(hb, q2.x, accB[4]);
            accA[5] = ffma2(ha, q2.y, accA[5]);  accB[5] = ffma2(hb, q2.y, accB[5]);
        }

#pragma unroll
        for (int p = 0; p < 6; p++) {
            const float2 uA = upk2(accA[p]);
            const float2 uB = upk2(accB[p]);
            const float al0 = c_head[5052 + 2 * p], al1 = c_head[5053 + 2 * p];
            float a0v = uA.x, a1v = uA.y, b0v = uB.x, b1v = uB.y;
            a0v = (a0v >= 0.f) ? a0v : al0 * a0v;
            a1v = (a1v >= 0.f) ? a1v : al1 * a1v;
            b0v = (b0v >= 0.f) ? b0v : al0 * b0v;
            b1v = (b1v >= 0.f) ? b1v : al1 * b1v;
            out[(2 * p) * 1024 + pixA]     = a0v;
            out[(2 * p + 1) * 1024 + pixA] = a1v;
            out[(2 * p) * 1024 + pixB]     = b0v;
            out[(2 * p + 1) * 1024 + pixB] = b1v;
        }
    }
}

// ---------------------------------------------------------------------------
// Kernel 2: four 3x3 convs (12->12, pad1), PReLU(b5_a) after the last.
// Padded 34x34 smem image; f32x2 over oc-pairs, weights [l][ic][tap][oc12].
// ---------------------------------------------------------------------------
__global__ __launch_bounds__(256, 2) void k_body(
    const float* __restrict__ w1, const float* __restrict__ bb1,
    const float* __restrict__ w2, const float* __restrict__ bb2,
    const float* __restrict__ w3, const float* __restrict__ bb3,
    const float* __restrict__ w4, const float* __restrict__ bb4,
    const float* __restrict__ b5a)
{
    extern __shared__ float sm[];
    float* buf = sm;               // 12*1156 = 13872 (34x34 padded)
    float* ws  = sm + 13872;       // 4*1296 = 5184, [l][ic][tap9][oc12]
    float* bs  = sm + 19056;       // 48
    float* a5  = sm + 19104;       // 12

    const int tid = threadIdx.x;
    const int img = blockIdx.x;

    const float* wl[4] = {w1, w2, w3, w4};
    const float* bl[4] = {bb1, bb2, bb3, bb4};
    for (int i = tid; i < 5184; i += 256) {
        const int l = i / 1296;
        const int r = i % 1296;
        const int ic = r / 108;
        const int r2 = r % 108;
        const int t = r2 / 12;
        const int oc = r2 % 12;
        ws[i] = wl[l][(oc * 12 + ic) * 9 + t];
    }
    if (tid < 48) bs[tid] = bl[tid / 12][tid % 12];
    if (tid < 12) a5[tid] = b5a[tid];

    for (int i = tid; i < 13872; i += 256) buf[i] = 0.f;
    __syncthreads();

    const float* src_g = g_h1 + img * 12288;
    for (int i = tid; i < 12288; i += 256) {
        const int c = i >> 10, p = i & 1023;
        const int y = p >> 5, xx = p & 31;
        buf[c * 1156 + (y + 1) * 34 + (xx + 1)] = src_g[i];
    }
    __syncthreads();

    const int x = tid & 31;
    const int y0 = tid >> 5;
    int base[4];
#pragma unroll
    for (int k = 0; k < 4; k++) base[k] = (y0 + 8 * k + 1) * 34 + (x + 1);

    float* gout = g_h5 + img * 12288;

#pragma unroll 1
    for (int l = 0; l < 4; l++) {
        const float* wsl = ws + l * 1296;
        const float* bb = bs + l * 12;

        ull acc2[4][6];
#pragma unroll
        for (int k = 0; k < 4; k++)
#pragma unroll
            for (int p = 0; p < 6; p++) acc2[k][p] = pk2(bb[2 * p], bb[2 * p + 1]);

#pragma unroll 1
        for (int ic = 0; ic < 12; ic++) {
            const float* cb = buf + ic * 1156;
            float n[4][9];
#pragma unroll
            for (int k = 0; k < 4; k++) {
                const float* sp = cb + base[k];
                n[k][0] = sp[-35]; n[k][1] = sp[-34]; n[k][2] = sp[-33];
                n[k][3] = sp[-1];  n[k][4] = sp[0];   n[k][5] = sp[1];
                n[k][6] = sp[33];  n[k][7] = sp[34];  n[k][8] = sp[35];
            }
            const float* wic = wsl + ic * 108;
#pragma unroll
            for (int t = 0; t < 9; t++) {
                const ulonglong2* wt = (const ulonglong2*)(wic + t * 12);
                const ulonglong2 wA = wt[0];
                const ull wC = *(const ull*)(wic + t * 12 + 4);
                const ulonglong2 wB = *(const ulonglong2*)(wic + t * 12 + 6);
#pragma unroll
                for (int k = 0; k < 4; k++) {
                    const ull nb = pk2(n[k][t], n[k][t]);
                    acc2[k][0] = ffma2(nb, wA.x, acc2[k][0]);
                    acc2[k][1] = ffma2(nb, wA.y, acc2[k][1]);
                    acc2[k][2] = ffma2(nb, wC,   acc2[k][2]);
                    acc2[k][3] = ffma2(nb, wB.x, acc2[k][3]);
                    acc2[k][4] = ffma2(nb, wB.y, acc2[k][4]);
                    acc2[k][5] = ffma2(nb, *(const ull*)(wic + t * 12 + 10), acc2[k][5]);
                }
            }
        }

        if (l == 3) {
#pragma unroll
            for (int k = 0; k < 4; k++) {
                const int pix = k * 256 + tid;
#pragma unroll
                for (int p = 0; p < 6; p++) {
                    const float2 u = upk2(acc2[k][p]);
                    float v0 = u.x, v1 = u.y;
                    v0 = (v0 >= 0.f) ? v0 : a5[2 * p] * v0;
                    v1 = (v1 >= 0.f) ? v1 : a5[2 * p + 1] * v1;
                    gout[(2 * p) * 1024 + pix]     = v0;
                    gout[(2 * p + 1) * 1024 + pix] = v1;
                }
            }
        } else {
            __syncthreads();
#pragma unroll
            for (int k = 0; k < 4; k++)
#pragma unroll
                for (int p = 0; p < 6; p++) {
                    const float2 u = upk2(acc2[k][p]);
                    buf[(2 * p) * 1156 + base[k]]     = u.x;
                    buf[(2 * p + 1) * 1156 + base[k]] = u.y;
                }
            __syncthreads();
        }
    }
}

// ---------------------------------------------------------------------------
// Kernel 3: b6 1x1 (12->56) + PReLU in smem, then 9x9 stride-2 transposed
// conv (56->3). 512 threads, 2 HORIZONTALLY-ADJACENT sites per thread
// ((sy,2m),(sy,2m+1)) -> shared h columns (6 loads cover both sites' 5 taps)
// AND shared tap weights. h6c layout [row36][blk18][60]: column pair packed
// per 60-float block (odd group stride -> conflict-free LDS.128).
// ---------------------------------------------------------------------------
__device__ __forceinline__ void cls2(const ulonglong2 h0, const ulonglong2 h1,
                                     const float* wt, int g, ull* P)
{
    const ulonglong2 w0 = *(const ulonglong2*)(wt + g);
    const ulonglong2 w1 = *(const ulonglong2*)(wt + 28 + g);
    const ulonglong2 w2 = *(const ulonglong2*)(wt + 56 + g);
    P[0] = ffma2(h0.x, w0.x, P[0]); P[0] = ffma2(h0.y, w0.y, P[0]);
    P[1] = ffma2(h0.x, w1.x, P[1]); P[1] = ffma2(h0.y, w1.y, P[1]);
    P[2] = ffma2(h0.x, w2.x, P[2]); P[2] = ffma2(h0.y, w2.y, P[2]);
    P[3] = ffma2(h1.x, w0.x, P[3]); P[3] = ffma2(h1.y, w0.y, P[3]);
    P[4] = ffma2(h1.x, w1.x, P[4]); P[4] = ffma2(h1.y, w1.y, P[4]);
    P[5] = ffma2(h1.x, w2.x, P[5]); P[5] = ffma2(h1.y, w2.y, P[5]);
}

__global__ __launch_bounds__(512, 1) void k_tail(
    const float* __restrict__ b6_w, const float* __restrict__ b6_b,
    const float* __restrict__ b6_a,
    const float* __restrict__ tail_w, const float* __restrict__ tail_b,
    float* __restrict__ out)
{
    extern __shared__ float sm[];
    float* h6c = sm;            // 36*18*60 = 38880  [row][blk][60]
    float* wtc = sm + 38880;    // 81*3*28 = 6804    [tap][oc][cl]
    float* b6w = sm + 45684;    // 672
    float* b6b = sm + 46356;    // 56
    float* b6a = sm + 46412;    // 56
    float* tb  = sm + 46468;    // 4
    // total 46472 floats = 185888 B

    const int tid = threadIdx.x;
    const int img = blockIdx.x;

    const float* h5g = g_h5 + img * 12288;

    for (int i = tid; i < 672; i += 512) b6w[i] = b6_w[i];
    if (tid < 56) { b6b[tid] = b6_b[tid]; b6a[tid] = b6_a[tid]; }
    if (tid < 3) tb[tid] = tail_b[tid];
    __syncthreads();

    const int sy = tid >> 4;     // 0..31
    const int m  = tid & 15;     // site cols 2m, 2m+1

    ull acc[4][6];   // [parity ry*2+rx][site0 oc0..2, site1 oc0..2]
#pragma unroll
    for (int p = 0; p < 4; p++)
#pragma unroll
        for (int o = 0; o < 6; o++) acc[p][o] = 0ULL;

#pragma unroll 1
    for (int cc = 0; cc < 2; cc++) {
        const int cb56 = cc * 28;
        if (cc) __syncthreads();    // protect wtc/h6c from previous readers

        // stage tail-weight chunk [tap81][oc3][cl28]
        for (int i = tid; i < 6804; i += 512) {
            const int tap = i / 84;
            const int rest = i % 84;
            const int oc = rest / 28;
            const int cl = rest % 28;
            wtc[i] = tail_w[(cb56 + cl) * 243 + oc * 81 + tap];
        }

        // phase A: expand 12 -> 28 channels for up to 3 tile pixels.
#pragma unroll 1
        for (int pp = 0; pp < 3; pp++) {
            const int p = tid + pp * 512;
            if (p >= 1296) break;
            const int r = p / 36, s = p % 36;
            const int iy = r - 2, ix = s - 2;
            const bool valid = (iy >= 0) & (iy < 32) & (ix >= 0) & (ix < 32);
            const float* gp = h5g + iy * 32 + ix;
            float v[12];
#pragma unroll
            for (int c = 0; c < 12; c++)
                v[c] = valid ? __ldg(gp + c * 1024) : 0.f;

            float* hout = h6c + r * 1080 + (s >> 1) * 60 + (s & 1) * 28;
#pragma unroll 1
            for (int cl = 0; cl < 28; cl++) {
                const int c = cb56 + cl;
                const float4* wq = (const float4*)(b6w + c * 12);
                const float4 q0 = wq[0], q1 = wq[1], q2 = wq[2];
                float a = b6b[c];
                a = fmaf(v[0], q0.x, a);  a = fmaf(v[1], q0.y, a);
                a = fmaf(v[2], q0.z, a);  a = fmaf(v[3], q0.w, a);
                a = fmaf(v[4], q1.x, a);  a = fmaf(v[5], q1.y, a);
                a = fmaf(v[6], q1.z, a);  a = fmaf(v[7], q1.w, a);
                a = fmaf(v[8], q2.x, a);  a = fmaf(v[9], q2.y, a);
                a = fmaf(v[10], q2.z, a); a = fmaf(v[11], q2.w, a);
                a = (a >= 0.f) ? a : b6a[c] * a;
                hout[cl] = valid ? a : 0.f;
            }
        }
        __syncthreads();

        // phase B: 5 rows x 6 shared h-columns; taps map to both sites.
        // dr = 0 (ky=8 only)
        {
            const float* hr = h6c + sy * 1080 + m * 60;
            const float* wk = wtc + (8 * 9) * 84;
#pragma unroll 1
            for (int g = 0; g < 28; g += 4) {
                const ulonglong2 hA0 = *(const ulonglong2*)(hr + g);
                const ulonglong2 hA1 = *(const ulonglong2*)(hr + 28 + g);
                const ulonglong2 hB0 = *(const ulonglong2*)(hr + 60 + g);
                const ulonglong2 hB1 = *(const ulonglong2*)(hr + 88 + g);
                const ulonglong2 hC0 = *(const ulonglong2*)(hr + 120 + g);
                const ulonglong2 hC1 = *(const ulonglong2*)(hr + 148 + g);
                cls2(hA0, hA1, wk + 8 * 84, g, acc[0]);
                cls2(hA1, hB0, wk + 6 * 84, g, acc[0]);
                cls2(hA1, hB0, wk + 7 * 84, g, acc[1]);
                cls2(hB0, hB1, wk + 4 * 84, g, acc[0]);
                cls2(hB0, hB1, wk + 5 * 84, g, acc[1]);
                cls2(hB1, hC0, wk + 2 * 84, g, acc[0]);
                cls2(hB1, hC0, wk + 3 * 84, g, acc[1]);
                cls2(hC0, hC1, wk + 0 * 84, g, acc[0]);
                cls2(hC0, hC1, wk + 1 * 84, g, acc[1]);
            }
        }
#pragma unroll 1
        for (int dr = 1; dr < 5; dr++) {
            const int ky0 = 8 - 2 * dr, ky1 = 9 - 2 * dr;
            const float* hr = h6c + (sy + dr) * 1080 + m * 60;
            const float* w0r = wtc + ky0 * 9 * 84;
            const float* w1r = wtc + ky1 * 9 * 84;
#pragma unroll 1
            for (int g = 0; g < 28; g += 4) {
                const ulonglong2 hA0 = *(const ulonglong2*)(hr + g);
                const ulonglong2 hA1 = *(const ulonglong2*)(hr + 28 + g);
                const ulonglong2 hB0 = *(const ulonglong2*)(hr + 60 + g);
                const ulonglong2 hB1 = *(const ulonglong2*)(hr + 88 + g);
                const ulonglong2 hC0 = *(const ulonglong2*)(hr + 120 + g);
                const ulonglong2 hC1 = *(const ulonglong2*)(hr + 148 + g);
                cls2(hA0, hA1, w0r + 8 * 84, g, acc[0]);
                cls2(hA1, hB0, w0r + 6 * 84, g, acc[0]);
                cls2(hA1, hB0, w0r + 7 * 84, g, acc[1]);
                cls2(hB0, hB1, w0r + 4 * 84, g, acc[0]);
                cls2(hB0, hB1, w0r + 5 * 84, g, acc[1]);
                cls2(hB1, hC0, w0r + 2 * 84, g, acc[0]);
                cls2(hB1, hC0, w0r + 3 * 84, g, acc[1]);
                cls2(hC0, hC1, w0r + 0 * 84, g, acc[0]);
                cls2(hC0, hC1, w0r + 1 * 84, g, acc[1]);

                cls2(hA0, hA1, w1r + 8 * 84, g, acc[2]);
                cls2(hA1, hB0, w1r + 6 * 84, g, acc[2]);
                cls2(hA1, hB0, w1r + 7 * 84, g, acc[3]);
                cls2(hB0, hB1, w1r + 4 * 84, g, acc[2]);
                cls2(hB0, hB1, w1r + 5 * 84, g, acc[3]);
                cls2(hB1, hC0, w1r + 2 * 84, g, acc[2]);
                cls2(hB1, hC0, w1r + 3 * 84, g, acc[3]);
                cls2(hC0, hC1, w1r + 0 * 84, g, acc[2]);
                cls2(hC0, hC1, w1r + 1 * 84, g, acc[3]);
            }
        }
    }

    float* o = out + img * 3 * 4096;
#pragma unroll
    for (int par = 0; par < 4; par++) {
        const int ry = par >> 1, rx = par & 1;
        const int oy = 2 * sy + ry;
        const int ox0 = 4 * m + rx;       // site0 (col 2m)
        const int ox1 = 4 * m + 2 + rx;   // site1 (col 2m+1)
#pragma unroll
        for (int oc = 0; oc < 3; oc++) {
            const float2 u0 = upk2(acc[par][oc]);
            const float2 u1 = upk2(acc[par][3 + oc]);
            o[oc * 4096 + oy * 64 + ox0] = tb[oc] + (u0.x + u0.y);
            o[oc * 4096 + oy * 64 + ox1] = tb[oc] + (u1.x + u1.y);
        }
    }
}

// ---------------------------------------------------------------------------
extern "C" void kernel_launch(void* const* d_in, const int* in_sizes, int n_in,
                              void* d_out, int out_size)
{
    const float* x      = (const float*)d_in[0];
    const float* head_w = (const float*)d_in[1];
    const float* head_b = (const float*)d_in[2];
    const float* head_a = (const float*)d_in[3];
    const float* b0_w   = (const float*)d_in[4];
    const float* b0_b   = (const float*)d_in[5];
    const float* b0_a   = (const float*)d_in[6];
    const float* b1_w   = (const float*)d_in[7];
    const float* b1_b   = (const float*)d_in[8];
    const float* b2_w   = (const float*)d_in[9];
    const float* b2_b   = (const float*)d_in[10];
    const float* b3_w   = (const float*)d_in[11];
    const float* b3_b   = (const float*)d_in[12];
    const float* b4_w   = (const float*)d_in[13];
    const float* b4_b   = (const float*)d_in[14];
    const float* b5_a   = (const float*)d_in[15];
    const float* b6_w   = (const float*)d_in[16];
    const float* b6_b   = (const float*)d_in[17];
    const float* b6_a   = (const float*)d_in[18];
    const float* tail_w = (const float*)d_in[19];
    const float* tail_b = (const float*)d_in[20];

    const int SM2 = 19116 * 4;   // k_body dynamic smem (76.5 KB)
    const int SM4 = 46472 * 4;   // k_tail dynamic smem (185.9 KB)
    cudaFuncSetAttribute(k_body, cudaFuncAttributeMaxDynamicSharedMemorySize, SM2);
    cudaFuncSetAttribute(k_tail, cudaFuncAttributeMaxDynamicSharedMemorySize, SM4);

    // stage head weights into constant bank (graph-capturable D2D copy)
    k_prep<<<20, 256>>>(head_w, head_b, head_a, b0_w, b0_b, b0_a);
    void* gsrc = nullptr;  cudaGetSymbolAddress(&gsrc, g_cpack);
    void* cdst = nullptr;  cudaGetSymbolAddress(&cdst, c_head);
    cudaMemcpyAsync(cdst, gsrc, 5064 * sizeof(float), cudaMemcpyDeviceToDevice, 0);

    k_head<<<1024, 256>>>(x);
    k_body<<<1024, 256, SM2>>>(b1_w, b1_b, b2_w, b2_b, b3_w, b3_b, b4_w, b4_b, b5_a);
    k_tail<<<1024, 512, SM4>>>(b6_w, b6_b, b6_a, tail_w, tail_b, (float*)d_out);
}